// round 14
// baseline (speedup 1.0000x reference)
#include <cuda_runtime.h>
#include <cuda_fp16.h>
#include <math.h>
#include <cstdint>

#define NBLK 32
#define CAP 1024
#define DK 256
#define DH 768
#define NQ 8192
#define NPART 8   /* grid.y partitions of the 32 memory blocks */

typedef uint32_t u32;
typedef unsigned long long ull;

// scratch (device globals: no allocation allowed)
__device__ __half g_qh[NQ * DK];              // layernormed queries * 1/16, fp16
__device__ __half g_kh[NBLK * CAP * DK];      // keys, fp16
__device__ __half g_vth[NBLK * DK * CAP];     // values transposed [b][d][key], fp16
__device__ float  g_r[NPART * NQ * DK];       // retrieved partials per block-group
__device__ float  g_rs[NQ * DK];              // reduced retrieved values

__device__ __forceinline__ u32 packh2(float a, float b) {
    __half2 h = __floats2half2_rn(a, b);
    return *(u32*)&h;
}

// packed dual-fp32 FMA: d = a*b + d (exact fp32, 2 lanes per issue)
__device__ __forceinline__ void fma2(ull& d, ull a, ull b) {
    asm("fma.rn.f32x2 %0, %1, %2, %0;" : "+l"(d) : "l"(a), "l"(b));
}
__device__ __forceinline__ ull dup2(float a) {
    ull r; asm("mov.b64 %0, {%1, %1};" : "=l"(r) : "f"(a)); return r;
}

// fp16 tensor-core mma, fp32 accumulate
__device__ __forceinline__ void mma_f16(float* d,
    u32 a0, u32 a1, u32 a2, u32 a3, u32 b0, u32 b1)
{
    asm("mma.sync.aligned.m16n8k16.row.col.f32.f16.f16.f32 "
        "{%0,%1,%2,%3},{%4,%5,%6,%7},{%8,%9},{%0,%1,%2,%3};"
        : "+f"(d[0]), "+f"(d[1]), "+f"(d[2]), "+f"(d[3])
        : "r"(a0), "r"(a1), "r"(a2), "r"(a3), "r"(b0), "r"(b1));
}

__device__ __forceinline__ u32 s2u(const void* p) {
    u32 a;
    asm("{ .reg .u64 t; cvta.to.shared.u64 t, %1; cvt.u32.u64 %0, t; }"
        : "=r"(a) : "l"(p));
    return a;
}
__device__ __forceinline__ void cpa16(u32 dst, const void* src) {
    asm volatile("cp.async.cg.shared.global [%0], [%1], 16;"
                 :: "r"(dst), "l"(src) : "memory");
}
#define CPA_COMMIT() asm volatile("cp.async.commit_group;" ::: "memory")
#define CPA_WAIT1()  asm volatile("cp.async.wait_group 1;" ::: "memory")

#define LDSM4(r, a) asm volatile( \
    "ldmatrix.sync.aligned.m8n8.x4.shared.b16 {%0,%1,%2,%3}, [%4];" \
    : "=r"((r)[0]), "=r"((r)[1]), "=r"((r)[2]), "=r"((r)[3]) : "r"(a))

#define QUAD_BAR(id) asm volatile("bar.sync %0, %1;" :: "r"(id), "r"(128) : "memory")

// ---------------------------------------------------------------------------
// Kernel A: q = LayerNorm(hs @ Wk + bk) * ln_w + ln_b, scaled 1/16 -> fp16
// BM=32 (256 CTAs), 256 threads, f32x2 packed FMA.
// ---------------------------------------------------------------------------
__global__ __launch_bounds__(256) void qproj_ln_kernel(
    const float* __restrict__ hs, const float* __restrict__ Wk,
    const float* __restrict__ bk, const float* __restrict__ lnw,
    const float* __restrict__ lnb)
{
    __shared__ float As[32][16];
    __shared__ float Bs[16][256];
    const int tid = threadIdx.x;
    const int ty = tid >> 5;
    const int tx = tid & 31;
    const int m0 = blockIdx.x * 32;

    ull c2[4][4];
#pragma unroll
    for (int i = 0; i < 4; i++)
#pragma unroll
        for (int j = 0; j < 4; j++) c2[i][j] = 0ull;

    for (int k0 = 0; k0 < DH; k0 += 16) {
        if (tid < 128) {
            int r = tid >> 2, k4 = tid & 3;
            float4 v = *(const float4*)(hs + (size_t)(m0 + r) * DH + k0 + k4 * 4);
            *(float4*)(&As[r][k4 * 4]) = v;
        }
#pragma unroll
        for (int u = 0; u < 4; u++) {
            int idx4 = tid + u * 256;
            int kk = idx4 >> 6, c4 = idx4 & 63;
            float4 v = *(const float4*)(Wk + (size_t)(k0 + kk) * DK + c4 * 4);
            *(float4*)(&Bs[kk][c4 * 4]) = v;
        }
        __syncthreads();
#pragma unroll
        for (int kk = 0; kk < 16; kk++) {
            ull a2[4];
#pragma unroll
            for (int i = 0; i < 4; i++) a2[i] = dup2(As[ty * 4 + i][kk]);
            const ull* bp = (const ull*)&Bs[kk][tx * 8];
#pragma unroll
            for (int i = 0; i < 4; i++) {
                fma2(c2[i][0], a2[i], bp[0]);
                fma2(c2[i][1], a2[i], bp[1]);
                fma2(c2[i][2], a2[i], bp[2]);
                fma2(c2[i][3], a2[i], bp[3]);
            }
        }
        __syncthreads();
    }

    float c[4][8];
#pragma unroll
    for (int i = 0; i < 4; i++)
#pragma unroll
        for (int j = 0; j < 4; j++) {
            float2 f = *(float2*)&c2[i][j];
            c[i][2 * j] = f.x; c[i][2 * j + 1] = f.y;
        }

    float bkv[8], lw[8], lb[8];
#pragma unroll
    for (int j = 0; j < 8; j++) {
        int col = tx * 8 + j;
        bkv[j] = bk[col]; lw[j] = lnw[col]; lb[j] = lnb[col];
    }
#pragma unroll
    for (int i = 0; i < 4; i++)
#pragma unroll
        for (int j = 0; j < 8; j++) c[i][j] += bkv[j];

#pragma unroll
    for (int i = 0; i < 4; i++) {
        float s = 0.f;
#pragma unroll
        for (int j = 0; j < 8; j++) s += c[i][j];
#pragma unroll
        for (int o = 16; o > 0; o >>= 1) s += __shfl_xor_sync(0xffffffffu, s, o);
        float mu = s * (1.0f / 256.0f);
        float v = 0.f;
#pragma unroll
        for (int j = 0; j < 8; j++) { float d = c[i][j] - mu; v += d * d; }
#pragma unroll
        for (int o = 16; o > 0; o >>= 1) v += __shfl_xor_sync(0xffffffffu, v, o);
        float rs = rsqrtf(v * (1.0f / 256.0f) + 1e-5f);
        float out[8];
#pragma unroll
        for (int j = 0; j < 8; j++)
            out[j] = ((c[i][j] - mu) * rs * lw[j] + lb[j]) * 0.0625f;
        __half* dst = g_qh + (size_t)(m0 + ty * 4 + i) * DK + tx * 8;
        *(uint4*)dst = make_uint4(packh2(out[0], out[1]), packh2(out[2], out[3]),
                                  packh2(out[4], out[5]), packh2(out[6], out[7]));
    }
}

// ---------------------------------------------------------------------------
// Kernel P (fused prep): keys fp32->fp16, V transpose -> fp16 [b][d][key]
// ---------------------------------------------------------------------------
#define KH_BLOCKS  ((NBLK * CAP * DK) / (256 * 8))   /* 4096 */
#define VTH_BLOCKS ((DK / 32) * (CAP / 32) * NBLK)   /* 8192 */

__global__ __launch_bounds__(256) void prep_kernel(
    const float* __restrict__ mk, const float* __restrict__ mv)
{
    __shared__ float t[32][33];
    const int bx = blockIdx.x;
    if (bx < KH_BLOCKS) {
        size_t i = ((size_t)bx * 256 + threadIdx.x) * 8;
        float4 v0 = *(const float4*)(mk + i);
        float4 v1 = *(const float4*)(mk + i + 4);
        *(uint4*)(g_kh + i) = make_uint4(packh2(v0.x, v0.y), packh2(v0.z, v0.w),
                                         packh2(v1.x, v1.y), packh2(v1.z, v1.w));
    } else {
        int idx = bx - KH_BLOCKS;
        const int dt = idx & 7;
        const int kt = (idx >> 3) & 31;
        const int b  = idx >> 8;
        const int r = threadIdx.x >> 3, c4 = (threadIdx.x & 7) * 4;
        float4 v = *(const float4*)(mv + ((size_t)b * CAP + kt * 32 + r) * DK + dt * 32 + c4);
        t[r][c4] = v.x; t[r][c4 + 1] = v.y; t[r][c4 + 2] = v.z; t[r][c4 + 3] = v.w;
        __syncthreads();
        uint2 o = make_uint2(packh2(t[c4][r], t[c4 + 1][r]),
                             packh2(t[c4 + 2][r], t[c4 + 3][r]));
        *(uint2*)(g_vth + ((size_t)b * DK + dt * 32 + r) * CAP + kt * 32 + c4) = o;
    }
}

// ---------------------------------------------------------------------------
// Kernel B: per-block masked softmax attention. fp16 mma + ldmatrix,
// chunk = 64 keys, double-buffered cp.async, 256 threads (8 warps).
// P kept as REGISTER A-fragments (exp in regs, packed to half2) and
// exchanged through an 8KB conflict-free table, synced per 4-warp QUAD
// (named barrier) instead of a full-CTA barrier.
// QK: warp w -> m16 tile (mt=w>>1), key-half n32 (vh=w&1); k=256.
// PV: warp w -> rows quad q=w>>2 (m32), cols u=w&3 (n64); k=64 in 4 k16
//     groups, A-frags pulled from quad warps' published fragments.
// ---------------------------------------------------------------------------
#define QSTR 264
#define KSTR 264
#define VSTR 72
#define KBUF (64 * KSTR)     /* halves per K buffer  */
#define VBUF (256 * VSTR)    /* halves per Vt buffer */
#define ATTN_SMEM (512 + 64*QSTR*2 + 2*KBUF*2 + 2*VBUF*2 + 8192)

extern __shared__ char sm_raw[];

__global__ __launch_bounds__(256, 1) void attn_kernel(const int* __restrict__ usage)
{
    float*  Ls  = (float*)sm_raw;                 // [64][2]
    __half* Qs  = (__half*)(sm_raw + 512);        // [64][264]
    __half* Ks  = Qs + 64 * QSTR;                 // 2 x [64][264]
    __half* Vts = Ks + 2 * KBUF;                  // 2 x [256][72]
    u32*    Pex = (u32*)(Vts + 2 * VBUF);         // [8 j][256 thread]

    const u32 ks_u = s2u(Ks);
    const u32 vt_u = s2u(Vts);

    const int tid  = threadIdx.x;
    const int w    = tid >> 5;
    const int lane = tid & 31;
    const int t4   = lane >> 2;
    const int tq   = lane & 3;
    const int q0   = blockIdx.x * 64;
    const int b0   = blockIdx.y * (NBLK / NPART);

    const int mt = w >> 1;          // QK m16 tile
    const int vh = w & 1;           // QK key-half (n32)
    const int qd = w >> 2;          // PV row quad (m32)
    const int uc = w & 3;           // PV col group (n64)

    const int l15 = lane & 15, lh = lane >> 4;
    const u32 qa  = s2u(Qs) + (u32)(((mt * 16 + l15) * QSTR + lh * 8) * 2);
    const u32 kb0 = (u32)(((vh * 32 + l15) * KSTR + lh * 8) * 2);        // + ks_u + buf
    const u32 kb1 = kb0 + 16 * KSTR * 2;
    const u32 vb0 = (u32)(((uc * 64 + l15) * VSTR + lh * 8) * 2);        // + vt_u + buf

    // Q tile -> smem (once)
#pragma unroll
    for (int u = 0; u < 8; u++) {
        int idx = tid + u * 256;
        int row = idx >> 5, seg = idx & 31;
        uint4 v = *(const uint4*)(g_qh + ((size_t)(q0 + row) << 8) + seg * 8);
        *(uint4*)(Qs + row * QSTR + seg * 8) = v;
    }

    float O[2][8][4];
#pragma unroll
    for (int mm = 0; mm < 2; mm++)
#pragma unroll
        for (int nt = 0; nt < 8; nt++)
#pragma unroll
            for (int j = 0; j < 4; j++) O[mm][nt][j] = 0.f;

    // prefetch chunk 0 of block b0 into buffer 0
    {
        const __half* kg = g_kh + (size_t)b0 * CAP * DK;
        const __half* vg = g_vth + (size_t)b0 * DK * CAP;
#pragma unroll
        for (int u = 0; u < 8; u++) {
            int idx = tid + u * 256;
            int key = idx >> 5, seg = idx & 31;
            cpa16(ks_u + (key * KSTR + seg * 8) * 2, kg + (size_t)key * DK + seg * 8);
            int d = idx >> 3, sg = idx & 7;
            cpa16(vt_u + (d * VSTR + sg * 8) * 2, vg + (size_t)d * CAP + sg * 8);
        }
        CPA_COMMIT();
    }

    int it = 0;
    for (int bb = 0; bb < NBLK / NPART; bb++) {
        const int b = b0 + bb;
        const int use = __ldg(usage + b);
        const int nch = (use + 63) >> 6;

        float acc[2][8][4];
#pragma unroll
        for (int mm = 0; mm < 2; mm++)
#pragma unroll
            for (int nt = 0; nt < 8; nt++)
#pragma unroll
                for (int j = 0; j < 4; j++) acc[mm][nt][j] = 0.f;

        for (int ch = 0; ch < nch; ch++, it++) {
            const int buf = it & 1;
            const int c0 = ch * 64;

            __syncthreads();   // A: prev chunk fully consumed (PV, Pex reads)

            // prefetch next chunk (possibly next block) into buf^1
            {
                int nb = b, nc = c0 + 64;
                bool has = true;
                if (ch + 1 >= nch) {
                    if (bb + 1 < NBLK / NPART) { nb = b + 1; nc = 0; }
                    else has = false;
                }
                if (has) {
                    const int pb = buf ^ 1;
                    const __half* kg = g_kh + ((size_t)nb * CAP + nc) * DK;
                    const __half* vg = g_vth + (size_t)nb * DK * CAP + nc;
                    const u32 kd = ks_u + pb * KBUF * 2;
                    const u32 vd = vt_u + pb * VBUF * 2;
#pragma unroll
                    for (int u = 0; u < 8; u++) {
                        int idx = tid + u * 256;
                        int key = idx >> 5, seg = idx & 31;
                        cpa16(kd + (key * KSTR + seg * 8) * 2,
                              kg + (size_t)key * DK + seg * 8);
                        int d = idx >> 3, sg = idx & 7;
                        cpa16(vd + (d * VSTR + sg * 8) * 2,
                              vg + (size_t)d * CAP + sg * 8);
                    }
                }
                CPA_COMMIT();
                CPA_WAIT1();   // current chunk's group complete
            }
            __syncthreads();   // B: chunk data visible to all warps

            // ---- S = Q K^T : m16 x n32 over k=256, 4 chains ----
            const u32 kbase = ks_u + buf * KBUF * 2;
            float s[4][4];
#pragma unroll
            for (int nt = 0; nt < 4; nt++)
#pragma unroll
                for (int j = 0; j < 4; j++) s[nt][j] = 0.f;
#pragma unroll
            for (int kk = 0; kk < 16; kk++) {
                u32 A[4], B0[4], B1[4];
                LDSM4(A, qa + kk * 32);
                LDSM4(B0, kbase + kb0 + kk * 32);
                LDSM4(B1, kbase + kb1 + kk * 32);
                mma_f16(s[0], A[0], A[1], A[2], A[3], B0[0], B0[2]);
                mma_f16(s[1], A[0], A[1], A[2], A[3], B0[1], B0[3]);
                mma_f16(s[2], A[0], A[1], A[2], A[3], B1[0], B1[2]);
                mma_f16(s[3], A[0], A[1], A[2], A[3], B1[1], B1[3]);
            }

            // ---- mask + exp (regs) + row sums + publish P A-frags ----
            const int rem = use - c0;   // >= 1
            const int row = mt * 16 + t4;
            float p[4][4];
            float rs_lo = 0.f, rs_hi = 0.f;
#pragma unroll
            for (int nt = 0; nt < 4; nt++) {
                int col = vh * 32 + nt * 8 + 2 * tq;
                p[nt][0] = (col     < rem) ? __expf(s[nt][0]) : 0.f;
                p[nt][1] = (col + 1 < rem) ? __expf(s[nt][1]) : 0.f;
                p[nt][2] = (col     < rem) ? __expf(s[nt][2]) : 0.f;
                p[nt][3] = (col + 1 < rem) ? __expf(s[nt][3]) : 0.f;
                rs_lo += p[nt][0] + p[nt][1];
                rs_hi += p[nt][2] + p[nt][3];
            }
            rs_lo += __shfl_xor_sync(0xffffffffu, rs_lo, 1);
            rs_lo += __shfl_xor_sync(0xffffffffu, rs_lo, 2);
            rs_hi += __shfl_xor_sync(0xffffffffu, rs_hi, 1);
            rs_hi += __shfl_xor_sync(0xffffffffu, rs_hi, 2);
            if (tq == 0) {   // unique writer per (row, key-half)
                if (ch == 0) {
                    Ls[row * 2 + vh]       = rs_lo;
                    Ls[(row + 8) * 2 + vh] = rs_hi;
                } else {
                    Ls[row * 2 + vh]       += rs_lo;
                    Ls[(row + 8) * 2 + vh] += rs_hi;
                }
            }
            // publish A-frags: group g covers this warp's keys g*16..g*16+16
            {
                const int base = w * 32 + lane;
#pragma unroll
                for (int g = 0; g < 2; g++) {
                    Pex[(g * 4 + 0) * 256 + base] = packh2(p[2 * g][0],     p[2 * g][1]);
                    Pex[(g * 4 + 1) * 256 + base] = packh2(p[2 * g][2],     p[2 * g][3]);
                    Pex[(g * 4 + 2) * 256 + base] = packh2(p[2 * g + 1][0], p[2 * g + 1][1]);
                    Pex[(g * 4 + 3) * 256 + base] = packh2(p[2 * g + 1][2], p[2 * g + 1][3]);
                }
            }
            QUAD_BAR(qd + 1);   // sync only this row-quad's 4 warps

            // ---- acc += P @ V : rows q*32 (m32) x cols u*64 (n64), k=64 ----
            const u32 vbase = vt_u + buf * VBUF * 2;
#pragma unroll
            for (int G = 0; G < 4; G++) {           // k16 group within chunk
                const int svh = G >> 1, g = G & 1;
                const int w0 = qd * 4 + svh;        // source warp for mm=0
                const int w1 = w0 + 2;              // source warp for mm=1
                u32 A0[4], A1[4];
#pragma unroll
                for (int i = 0; i < 4; i++) {
                    A0[i] = Pex[(g * 4 + i) * 256 + w0 * 32 + lane];
                    A1[i] = Pex[(g * 4 + i) * 256 + w1 * 32 + lane];
                }
#pragma unroll
                for (int nt16 = 0; nt16 < 4; nt16++) {
                    u32 B[4];
                    LDSM4(B, vbase + vb0 + nt16 * 16 * VSTR * 2 + G * 32);
                    mma_f16(acc[0][2 * nt16],     A0[0], A0[1], A0[2], A0[3], B[0], B[2]);
                    mma_f16(acc[0][2 * nt16 + 1], A0[0], A0[1], A0[2], A0[3], B[1], B[3]);
                    mma_f16(acc[1][2 * nt16],     A1[0], A1[1], A1[2], A1[3], B[0], B[2]);
                    mma_f16(acc[1][2 * nt16 + 1], A1[0], A1[1], A1[2], A1[3], B[1], B[3]);
                }
            }
        }

        // ---- finalize block: O += acc / rowsum (Ls quad-visible) ----
#pragma unroll
        for (int mm = 0; mm < 2; mm++) {
            int r = qd * 32 + mm * 16 + t4;
            float il = 1.0f / (Ls[r * 2] + Ls[r * 2 + 1]);
            float ih = 1.0f / (Ls[(r + 8) * 2] + Ls[(r + 8) * 2 + 1]);
#pragma unroll
            for (int nt = 0; nt < 8; nt++) {
                O[mm][nt][0] += acc[mm][nt][0] * il;
                O[mm][nt][1] += acc[mm][nt][1] * il;
                O[mm][nt][2] += acc[mm][nt][2] * ih;
                O[mm][nt][3] += acc[mm][nt][3] * ih;
            }
        }
    }

    // write partial retrieved values for this block group
    float* dst = g_r + (size_t)blockIdx.y * NQ * DK;
#pragma unroll
    for (int mm = 0; mm < 2; mm++) {
        int r = q0 + qd * 32 + mm * 16 + t4;
#pragma unroll
        for (int nt = 0; nt < 8; nt++) {
            int col = uc * 64 + nt * 8 + 2 * tq;
            *(float2*)(dst + (size_t)r * DK + col) =
                make_float2(O[mm][nt][0], O[mm][nt][1]);
            *(float2*)(dst + (size_t)(r + 8) * DK + col) =
                make_float2(O[mm][nt][2], O[mm][nt][3]);
        }
    }
}

// ---------------------------------------------------------------------------
// Kernel R: reduce NPART partials -> g_rs
// ---------------------------------------------------------------------------
__global__ __launch_bounds__(256) void reduce_r_kernel()
{
    size_t i = ((size_t)blockIdx.x * 256 + threadIdx.x) * 4;
    float4 a = *(const float4*)(g_r + i);
#pragma unroll
    for (int p = 1; p < NPART; p++) {
        float4 b = *(const float4*)(g_r + (size_t)p * NQ * DK + i);
        a.x += b.x; a.y += b.y; a.z += b.z; a.w += b.w;
    }
    *(float4*)(g_rs + i) = a;
}

// ---------------------------------------------------------------------------
// Kernel C: out = g_rs @ Wo + bo   [8192,256]x[256,768], f32x2 packed FMA.
// ---------------------------------------------------------------------------
__global__ __launch_bounds__(256) void out_gemm_kernel(
    const float* __restrict__ Wo, const float* __restrict__ bo,
    float* __restrict__ out)
{
    __shared__ float As[64][20];
    __shared__ float Bs[16][64];
    const int tid = threadIdx.x;
    const int ty = tid >> 4;
    const int tx = tid & 15;
    const int m0 = blockIdx.x * 64;
    const int n0 = blockIdx.y * 64;

    ull c2[4][2];
#pragma unroll
    for (int i = 0; i < 4; i++) { c2[i][0] = 0ull; c2[i][1] = 0ull; }

    for (int k0 = 0; k0 < DK; k0 += 16) {
        {
            int r = tid >> 2, k4 = tid & 3;
            float4 v = *(const float4*)(g_rs + (size_t)(m0 + r) * DK + k0 + k4 * 4);
            *(float4*)(&As[r][k4 * 4]) = v;
        }
        {
            int kk = tid >> 4, c4 = tid & 15;
            float4 v = *(const float4*)(Wo + (size_t)(k0 + kk) * DH + n0 + c4 * 4);
            *(float4*)(&Bs[kk][c4 * 4]) = v;
        }
        __syncthreads();
#pragma unroll
        for (int kk = 0; kk < 16; kk++) {
            ull a2[4];
#pragma unroll
            for (int i = 0; i < 4; i++) a2[i] = dup2(As[ty * 4 + i][kk]);
            const ull* bp = (const ull*)&Bs[kk][tx * 4];
#pragma unroll
            for (int i = 0; i < 4; i++) {
                fma2(c2[i][0], a2[i], bp[0]);
                fma2(c2[i][1], a2[i], bp[1]);
            }
        }
        __syncthreads();
    }

    float4 bv = *(const float4*)(bo + n0 + tx * 4);
#pragma unroll
    for (int i = 0; i < 4; i++) {
        float2 f0 = *(float2*)&c2[i][0];
        float2 f1 = *(float2*)&c2[i][1];
        float4 r = make_float4(f0.x + bv.x, f0.y + bv.y, f1.x + bv.z, f1.y + bv.w);
        *(float4*)(out + (size_t)(m0 + ty * 4 + i) * DH + n0 + tx * 4) = r;
    }
}

// ---------------------------------------------------------------------------
extern "C" void kernel_launch(void* const* d_in, const int* in_sizes, int n_in,
                              void* d_out, int out_size)
{
    const float* hs  = (const float*)d_in[0];
    const float* Wk  = (const float*)d_in[1];
    const float* bk  = (const float*)d_in[2];
    const float* lnw = (const float*)d_in[3];
    const float* lnb = (const float*)d_in[4];
    const float* mk  = (const float*)d_in[5];
    const float* mv  = (const float*)d_in[6];
    const float* Wo  = (const float*)d_in[7];
    const float* bo  = (const float*)d_in[8];
    const int* usage = (const int*)d_in[9];
    float* out = (float*)d_out;

    cudaFuncSetAttribute(attn_kernel, cudaFuncAttributeMaxDynamicSharedMemorySize,
                         ATTN_SMEM);

    qproj_ln_kernel<<<NQ / 32, 256>>>(hs, Wk, bk, lnw, lnb);
    prep_kernel<<<KH_BLOCKS + VTH_BLOCKS, 256>>>(mk, mv);
    attn_kernel<<<dim3(NQ / 64, NPART), 256, ATTN_SMEM>>>(usage);
    reduce_r_kernel<<<(NQ * DK) / (256 * 4), 256>>>();
    dim3 gc(NQ / 64, DH / 64);
    out_gemm_kernel<<<gc, 256>>>(Wo, bo, out);
}

// round 15
// speedup vs baseline: 1.2648x; 1.2648x over previous
#include <cuda_runtime.h>
#include <cuda_fp16.h>
#include <math.h>
#include <cstdint>

#define NBLK 32
#define CAP 1024
#define DK 256
#define DH 768
#define NQ 8192
#define NPART 8   /* grid.y partitions of the 32 memory blocks */

typedef uint32_t u32;

// scratch (device globals: no allocation allowed)
__device__ __half g_qh[NQ * DK];              // layernormed queries * 1/16, fp16
__device__ __half g_kh[NBLK * CAP * DK];      // keys, fp16
__device__ __half g_vth[NBLK * DK * CAP];     // values transposed [b][d][key], fp16
__device__ __half g_hsh[NQ * DH];             // hidden states, fp16
__device__ __half g_wkth[DK * DH];            // Wk^T  [n=256][k=768], fp16
__device__ __half g_woth[DH * DK];            // Wo^T  [n=768][k=256], fp16
__device__ float  g_r[NPART * NQ * DK];       // retrieved partials per block-group
__device__ __half g_rsh[NQ * DK];             // reduced retrieved values, fp16

__device__ __forceinline__ u32 packh2(float a, float b) {
    __half2 h = __floats2half2_rn(a, b);
    return *(u32*)&h;
}

// fp16 tensor-core mma, fp32 accumulate
__device__ __forceinline__ void mma_f16(float* d,
    u32 a0, u32 a1, u32 a2, u32 a3, u32 b0, u32 b1)
{
    asm("mma.sync.aligned.m16n8k16.row.col.f32.f16.f16.f32 "
        "{%0,%1,%2,%3},{%4,%5,%6,%7},{%8,%9},{%0,%1,%2,%3};"
        : "+f"(d[0]), "+f"(d[1]), "+f"(d[2]), "+f"(d[3])
        : "r"(a0), "r"(a1), "r"(a2), "r"(a3), "r"(b0), "r"(b1));
}

__device__ __forceinline__ u32 s2u(const void* p) {
    u32 a;
    asm("{ .reg .u64 t; cvta.to.shared.u64 t, %1; cvt.u32.u64 %0, t; }"
        : "=r"(a) : "l"(p));
    return a;
}
__device__ __forceinline__ void cpa16(u32 dst, const void* src) {
    asm volatile("cp.async.cg.shared.global [%0], [%1], 16;"
                 :: "r"(dst), "l"(src) : "memory");
}
#define CPA_COMMIT() asm volatile("cp.async.commit_group;" ::: "memory")
#define CPA_WAIT1()  asm volatile("cp.async.wait_group 1;" ::: "memory")

#define LDSM4(r, a) asm volatile( \
    "ldmatrix.sync.aligned.m8n8.x4.shared.b16 {%0,%1,%2,%3}, [%4];" \
    : "=r"((r)[0]), "=r"((r)[1]), "=r"((r)[2]), "=r"((r)[3]) : "r"(a))

// ---------------------------------------------------------------------------
// Kernel P (fused prep), roles by blockIdx.x:
//  [0, KH)            keys fp32 -> fp16
//  [KH, +VTH)         V transpose -> fp16 [b][d][key]
//  [.., +HS)          hidden_states fp32 -> fp16
//  [.., +WKT)         Wk [768][256] -> g_wkth [256][768] fp16
//  [.., +WOT)         Wo [256][768] -> g_woth [768][256] fp16
// ---------------------------------------------------------------------------
#define KH_BLOCKS  ((NBLK * CAP * DK) / (256 * 8))   /* 4096 */
#define VTH_BLOCKS ((DK / 32) * (CAP / 32) * NBLK)   /* 8192 */
#define HS_BLOCKS  ((NQ * DH) / (256 * 8))           /* 3072 */
#define WKT_BLOCKS ((DH / 32) * (DK / 32))           /* 192  */
#define WOT_BLOCKS ((DK / 32) * (DH / 32))           /* 192  */
#define PREP_GRID (KH_BLOCKS + VTH_BLOCKS + HS_BLOCKS + WKT_BLOCKS + WOT_BLOCKS)

// transpose one 32x32 tile: out[c][r] = in[r][c], fp32 -> fp16
__device__ __forceinline__ void tile_transpose(
    const float* __restrict__ in, __half* __restrict__ out,
    int R, int C, int rt, int ct, float t[32][33])
{
    const int r = threadIdx.x >> 3, c4 = (threadIdx.x & 7) * 4;
    float4 v = *(const float4*)(in + (size_t)(rt * 32 + r) * C + ct * 32 + c4);
    t[r][c4] = v.x; t[r][c4 + 1] = v.y; t[r][c4 + 2] = v.z; t[r][c4 + 3] = v.w;
    __syncthreads();
    uint2 o = make_uint2(packh2(t[c4][r], t[c4 + 1][r]),
                         packh2(t[c4 + 2][r], t[c4 + 3][r]));
    *(uint2*)(out + (size_t)(ct * 32 + r) * R + rt * 32 + c4) = o;
}

__global__ __launch_bounds__(256) void prep_kernel(
    const float* __restrict__ mk, const float* __restrict__ mv,
    const float* __restrict__ hs, const float* __restrict__ Wk,
    const float* __restrict__ Wo)
{
    __shared__ float t[32][33];
    int bx = blockIdx.x;
    if (bx < KH_BLOCKS) {
        size_t i = ((size_t)bx * 256 + threadIdx.x) * 8;
        float4 v0 = *(const float4*)(mk + i);
        float4 v1 = *(const float4*)(mk + i + 4);
        *(uint4*)(g_kh + i) = make_uint4(packh2(v0.x, v0.y), packh2(v0.z, v0.w),
                                         packh2(v1.x, v1.y), packh2(v1.z, v1.w));
        return;
    }
    bx -= KH_BLOCKS;
    if (bx < VTH_BLOCKS) {
        const int dt = bx & 7, kt = (bx >> 3) & 31, b = bx >> 8;
        tile_transpose(mv + (size_t)b * CAP * DK, g_vth + (size_t)b * DK * CAP,
                       CAP, DK, kt, dt, t);
        return;
    }
    bx -= VTH_BLOCKS;
    if (bx < HS_BLOCKS) {
        size_t i = ((size_t)bx * 256 + threadIdx.x) * 8;
        float4 v0 = *(const float4*)(hs + i);
        float4 v1 = *(const float4*)(hs + i + 4);
        *(uint4*)(g_hsh + i) = make_uint4(packh2(v0.x, v0.y), packh2(v0.z, v0.w),
                                          packh2(v1.x, v1.y), packh2(v1.z, v1.w));
        return;
    }
    bx -= HS_BLOCKS;
    if (bx < WKT_BLOCKS) {
        const int ct = bx & 7, rt = bx >> 3;   // Wk: R=768, C=256
        tile_transpose(Wk, g_wkth, DH, DK, rt, ct, t);
        return;
    }
    bx -= WKT_BLOCKS;
    {
        const int ct = bx % 24, rt = bx / 24;  // Wo: R=256, C=768
        tile_transpose(Wo, g_woth, DK, DH, rt, ct, t);
    }
}

// ---------------------------------------------------------------------------
// Kernel A: q = LayerNorm(hsh @ WkT + bk) * ln_w + ln_b, scaled 1/16 -> fp16
// fp16 tensor-core GEMM. CTA = 64 rows x full 256 cols, K=768 in 6 chunks
// of 128. 8 warps: mw=w&3 -> m16 tile, nh=w>>2 -> n128 half.
// LN via E[x^2]-mu^2 on fp32 accumulators (warp shfl + smem cross-half).
// ---------------------------------------------------------------------------
#define QP_ASTR 136
#define QP_SMEM (1024 + 64 * QP_ASTR * 2 + 256 * QP_ASTR * 2)

extern __shared__ char qp_raw[];

__global__ __launch_bounds__(256, 1) void qproj_ln_kernel(
    const float* __restrict__ bk, const float* __restrict__ lnw,
    const float* __restrict__ lnb)
{
    float*  Lq = (float*)qp_raw;                 // [64][2 halves][2 {sum,sq}]
    __half* As = (__half*)(qp_raw + 1024);       // [64][136]
    __half* Bs = As + 64 * QP_ASTR;              // [256][136]

    const int tid = threadIdx.x;
    const int w = tid >> 5, lane = tid & 31;
    const int t4 = lane >> 2, tq = lane & 3;
    const int mw = w & 3, nh = w >> 2;
    const int m0 = blockIdx.x * 64;

    const int l15 = lane & 15, lh = lane >> 4;
    const u32 qa = s2u(As) + (u32)(((mw * 16 + l15) * QP_ASTR + lh * 8) * 2);
    const u32 qb = s2u(Bs) + (u32)(((nh * 128 + l15) * QP_ASTR + lh * 8) * 2);

    float acc[16][4];
#pragma unroll
    for (int nt = 0; nt < 16; nt++)
#pragma unroll
        for (int j = 0; j < 4; j++) acc[nt][j] = 0.f;

    for (int kc = 0; kc < DH / 128; kc++) {
        const int k0 = kc * 128;
#pragma unroll
        for (int u = 0; u < 4; u++) {   // A: 64 x 16 uint4
            int idx = tid + u * 256;
            int row = idx >> 4, seg = idx & 15;
            *(uint4*)(As + row * QP_ASTR + seg * 8) =
                *(const uint4*)(g_hsh + (size_t)(m0 + row) * DH + k0 + seg * 8);
        }
#pragma unroll
        for (int u = 0; u < 16; u++) {  // B: 256 x 16 uint4
            int idx = tid + u * 256;
            int row = idx >> 4, seg = idx & 15;
            *(uint4*)(Bs + row * QP_ASTR + seg * 8) =
                *(const uint4*)(g_wkth + (size_t)row * DH + k0 + seg * 8);
        }
        __syncthreads();
#pragma unroll
        for (int kk = 0; kk < 8; kk++) {
            u32 A[4];
            LDSM4(A, qa + kk * 32);
#pragma unroll
            for (int nt16 = 0; nt16 < 8; nt16++) {
                u32 B[4];
                LDSM4(B, qb + nt16 * 16 * QP_ASTR * 2 + kk * 32);
                mma_f16(acc[2 * nt16],     A[0], A[1], A[2], A[3], B[0], B[2]);
                mma_f16(acc[2 * nt16 + 1], A[0], A[1], A[2], A[3], B[1], B[3]);
            }
        }
        __syncthreads();
    }

    // add bias, accumulate row sums + sumsq
    const int row = mw * 16 + t4;
    float slo = 0.f, sqlo = 0.f, shi = 0.f, sqhi = 0.f;
#pragma unroll
    for (int nt = 0; nt < 16; nt++) {
        int col = nh * 128 + nt * 8 + 2 * tq;
        float2 bkv = *(const float2*)(bk + col);
        acc[nt][0] += bkv.x; acc[nt][1] += bkv.y;
        acc[nt][2] += bkv.x; acc[nt][3] += bkv.y;
        slo += acc[nt][0] + acc[nt][1];
        sqlo += acc[nt][0] * acc[nt][0] + acc[nt][1] * acc[nt][1];
        shi += acc[nt][2] + acc[nt][3];
        sqhi += acc[nt][2] * acc[nt][2] + acc[nt][3] * acc[nt][3];
    }
#pragma unroll
    for (int o = 1; o <= 2; o <<= 1) {
        slo  += __shfl_xor_sync(0xffffffffu, slo, o);
        sqlo += __shfl_xor_sync(0xffffffffu, sqlo, o);
        shi  += __shfl_xor_sync(0xffffffffu, shi, o);
        sqhi += __shfl_xor_sync(0xffffffffu, sqhi, o);
    }
    if (tq == 0) {
        Lq[row * 4 + nh * 2]           = slo;
        Lq[row * 4 + nh * 2 + 1]       = sqlo;
        Lq[(row + 8) * 4 + nh * 2]     = shi;
        Lq[(row + 8) * 4 + nh * 2 + 1] = sqhi;
    }
    __syncthreads();

    float mu0, rs0, mu1, rs1;
    {
        float s = Lq[row * 4] + Lq[row * 4 + 2];
        float q = Lq[row * 4 + 1] + Lq[row * 4 + 3];
        mu0 = s * (1.0f / 256.0f);
        rs0 = rsqrtf(q * (1.0f / 256.0f) - mu0 * mu0 + 1e-5f);
        s = Lq[(row + 8) * 4] + Lq[(row + 8) * 4 + 2];
        q = Lq[(row + 8) * 4 + 1] + Lq[(row + 8) * 4 + 3];
        mu1 = s * (1.0f / 256.0f);
        rs1 = rsqrtf(q * (1.0f / 256.0f) - mu1 * mu1 + 1e-5f);
    }
#pragma unroll
    for (int nt = 0; nt < 16; nt++) {
        int col = nh * 128 + nt * 8 + 2 * tq;
        float2 lw = *(const float2*)(lnw + col);
        float2 lb = *(const float2*)(lnb + col);
        float o0 = ((acc[nt][0] - mu0) * rs0 * lw.x + lb.x) * 0.0625f;
        float o1 = ((acc[nt][1] - mu0) * rs0 * lw.y + lb.y) * 0.0625f;
        float o2 = ((acc[nt][2] - mu1) * rs1 * lw.x + lb.x) * 0.0625f;
        float o3 = ((acc[nt][3] - mu1) * rs1 * lw.y + lb.y) * 0.0625f;
        *(u32*)(g_qh + (size_t)(m0 + row) * DK + col)     = packh2(o0, o1);
        *(u32*)(g_qh + (size_t)(m0 + row + 8) * DK + col) = packh2(o2, o3);
    }
}

// ---------------------------------------------------------------------------
// Kernel B: per-block masked softmax attention (R13 proven loop, unchanged).
// ---------------------------------------------------------------------------
#define QSTR 264
#define KSTR 264
#define VSTR 72
#define PSTR 72
#define KBUF (64 * KSTR)
#define VBUF (256 * VSTR)
#define ATTN_SMEM (512 + 64*QSTR*2 + 2*KBUF*2 + 2*VBUF*2 + 64*PSTR*2)

extern __shared__ char sm_raw[];

__global__ __launch_bounds__(256, 1) void attn_kernel(const int* __restrict__ usage)
{
    float*  Ls  = (float*)sm_raw;                 // [64][2]
    __half* Qs  = (__half*)(sm_raw + 512);        // [64][264]
    __half* Ks  = Qs + 64 * QSTR;                 // 2 x [64][264]
    __half* Vts = Ks + 2 * KBUF;                  // 2 x [256][72]
    __half* Ps  = Vts + 2 * VBUF;                 // [64][72]

    const u32 ks_u = s2u(Ks);
    const u32 vt_u = s2u(Vts);

    const int tid  = threadIdx.x;
    const int w    = tid >> 5;
    const int lane = tid & 31;
    const int t4   = lane >> 2;
    const int tq   = lane & 3;
    const int q0   = blockIdx.x * 64;
    const int b0   = blockIdx.y * (NBLK / NPART);

    const int mw = w >> 1;
    const int nh = w & 1;
    const int mg = w & 1;
    const int ng = w >> 1;

    const int l15 = lane & 15, lh = lane >> 4;
    const u32 qa  = s2u(Qs) + (u32)(((mw * 16 + l15) * QSTR + lh * 8) * 2);
    const u32 kb0 = (u32)(((nh * 32 + l15) * KSTR + lh * 8) * 2);
    const u32 kb1 = kb0 + 16 * KSTR * 2;
    const u32 pa0 = s2u(Ps) + (u32)(((mg * 32 + l15) * PSTR + lh * 8) * 2);
    const u32 pa1 = pa0 + 16 * PSTR * 2;
    const u32 vb0 = (u32)(((ng * 64 + l15) * VSTR + lh * 8) * 2);

#pragma unroll
    for (int u = 0; u < 8; u++) {
        int idx = tid + u * 256;
        int row = idx >> 5, seg = idx & 31;
        uint4 v = *(const uint4*)(g_qh + ((size_t)(q0 + row) << 8) + seg * 8);
        *(uint4*)(Qs + row * QSTR + seg * 8) = v;
    }

    float O[2][8][4];
#pragma unroll
    for (int mt = 0; mt < 2; mt++)
#pragma unroll
        for (int nt = 0; nt < 8; nt++)
#pragma unroll
            for (int j = 0; j < 4; j++) O[mt][nt][j] = 0.f;

    {
        const __half* kg = g_kh + (size_t)b0 * CAP * DK;
        const __half* vg = g_vth + (size_t)b0 * DK * CAP;
#pragma unroll
        for (int u = 0; u < 8; u++) {
            int idx = tid + u * 256;
            int key = idx >> 5, seg = idx & 31;
            cpa16(ks_u + (key * KSTR + seg * 8) * 2, kg + (size_t)key * DK + seg * 8);
            int d = idx >> 3, sg = idx & 7;
            cpa16(vt_u + (d * VSTR + sg * 8) * 2, vg + (size_t)d * CAP + sg * 8);
        }
        CPA_COMMIT();
    }

    int it = 0;
    for (int bb = 0; bb < NBLK / NPART; bb++) {
        const int b = b0 + bb;
        const int use = __ldg(usage + b);
        const int nch = (use + 63) >> 6;

        float acc[2][8][4];
#pragma unroll
        for (int mt = 0; mt < 2; mt++)
#pragma unroll
            for (int nt = 0; nt < 8; nt++)
#pragma unroll
                for (int j = 0; j < 4; j++) acc[mt][nt][j] = 0.f;

        for (int ch = 0; ch < nch; ch++, it++) {
            const int buf = it & 1;
            const int c0 = ch * 64;

            __syncthreads();

            {
                int nb = b, nc = c0 + 64;
                bool has = true;
                if (ch + 1 >= nch) {
                    if (bb + 1 < NBLK / NPART) { nb = b + 1; nc = 0; }
                    else has = false;
                }
                if (has) {
                    const int pb = buf ^ 1;
                    const __half* kg = g_kh + ((size_t)nb * CAP + nc) * DK;
                    const __half* vg = g_vth + (size_t)nb * DK * CAP + nc;
                    const u32 kd = ks_u + pb * KBUF * 2;
                    const u32 vd = vt_u + pb * VBUF * 2;
#pragma unroll
                    for (int u = 0; u < 8; u++) {
                        int idx = tid + u * 256;
                        int key = idx >> 5, seg = idx & 31;
                        cpa16(kd + (key * KSTR + seg * 8) * 2,
                              kg + (size_t)key * DK + seg * 8);
                        int d = idx >> 3, sg = idx & 7;
                        cpa16(vd + (d * VSTR + sg * 8) * 2,
                              vg + (size_t)d * CAP + sg * 8);
                    }
                }
                CPA_COMMIT();
                CPA_WAIT1();
            }
            __syncthreads();

            const u32 kbase = ks_u + buf * KBUF * 2;
            float s[4][4];
#pragma unroll
            for (int nt = 0; nt < 4; nt++)
#pragma unroll
                for (int j = 0; j < 4; j++) s[nt][j] = 0.f;
#pragma unroll
            for (int kk = 0; kk < 16; kk++) {
                u32 A[4], B0[4], B1[4];
                LDSM4(A, qa + kk * 32);
                LDSM4(B0, kbase + kb0 + kk * 32);
                LDSM4(B1, kbase + kb1 + kk * 32);
                mma_f16(s[0], A[0], A[1], A[2], A[3], B0[0], B0[2]);
                mma_f16(s[1], A[0], A[1], A[2], A[3], B0[1], B0[3]);
                mma_f16(s[2], A[0], A[1], A[2], A[3], B1[0], B1[2]);
                mma_f16(s[3], A[0], A[1], A[2], A[3], B1[1], B1[3]);
            }

            const int rem = use - c0;
            const int row = mw * 16 + t4;
            float rs_lo = 0.f, rs_hi = 0.f;
#pragma unroll
            for (int nt = 0; nt < 4; nt++) {
                int col = nh * 32 + nt * 8 + 2 * tq;
                float p0 = (col     < rem) ? __expf(s[nt][0]) : 0.f;
                float p1 = (col + 1 < rem) ? __expf(s[nt][1]) : 0.f;
                float p2 = (col     < rem) ? __expf(s[nt][2]) : 0.f;
                float p3 = (col + 1 < rem) ? __expf(s[nt][3]) : 0.f;
                rs_lo += p0 + p1;
                rs_hi += p2 + p3;
                *(u32*)(Ps + row * PSTR + col)       = packh2(p0, p1);
                *(u32*)(Ps + (row + 8) * PSTR + col) = packh2(p2, p3);
            }
            rs_lo += __shfl_xor_sync(0xffffffffu, rs_lo, 1);
            rs_lo += __shfl_xor_sync(0xffffffffu, rs_lo, 2);
            rs_hi += __shfl_xor_sync(0xffffffffu, rs_hi, 1);
            rs_hi += __shfl_xor_sync(0xffffffffu, rs_hi, 2);
            if (tq == 0) {
                if (ch == 0) {
                    Ls[row * 2 + nh]       = rs_lo;
                    Ls[(row + 8) * 2 + nh] = rs_hi;
                } else {
                    Ls[row * 2 + nh]       += rs_lo;
                    Ls[(row + 8) * 2 + nh] += rs_hi;
                }
            }
            __syncthreads();

            const u32 vbase = vt_u + buf * VBUF * 2;
#pragma unroll
            for (int kk = 0; kk < 4; kk++) {
                u32 A0[4], A1[4];
                LDSM4(A0, pa0 + kk * 32);
                LDSM4(A1, pa1 + kk * 32);
#pragma unroll
                for (int nt = 0; nt < 4; nt++) {
                    u32 B[4];
                    LDSM4(B, vbase + vb0 + nt * 16 * VSTR * 2 + kk * 32);
                    mma_f16(acc[0][2 * nt],     A0[0], A0[1], A0[2], A0[3], B[0], B[2]);
                    mma_f16(acc[0][2 * nt + 1], A0[0], A0[1], A0[2], A0[3], B[1], B[3]);
                    mma_f16(acc[1][2 * nt],     A1[0], A1[1], A1[2], A1[3], B[0], B[2]);
                    mma_f16(acc[1][2 * nt + 1], A1[0], A1[1], A1[2], A1[3], B[1], B[3]);
                }
            }
        }

#pragma unroll
        for (int mt = 0; mt < 2; mt++) {
            int r = mg * 32 + mt * 16 + t4;
            float il = 1.0f / (Ls[r * 2] + Ls[r * 2 + 1]);
            float ih = 1.0f / (Ls[(r + 8) * 2] + Ls[(r + 8) * 2 + 1]);
#pragma unroll
            for (int nt = 0; nt < 8; nt++) {
                O[mt][nt][0] += acc[mt][nt][0] * il;
                O[mt][nt][1] += acc[mt][nt][1] * il;
                O[mt][nt][2] += acc[mt][nt][2] * ih;
                O[mt][nt][3] += acc[mt][nt][3] * ih;
            }
        }
    }

    float* dst = g_r + (size_t)blockIdx.y * NQ * DK;
#pragma unroll
    for (int mt = 0; mt < 2; mt++) {
        int r = q0 + mg * 32 + mt * 16 + t4;
#pragma unroll
        for (int nt = 0; nt < 8; nt++) {
            int col = ng * 64 + nt * 8 + 2 * tq;
            *(float2*)(dst + (size_t)r * DK + col) =
                make_float2(O[mt][nt][0], O[mt][nt][1]);
            *(float2*)(dst + (size_t)(r + 8) * DK + col) =
                make_float2(O[mt][nt][2], O[mt][nt][3]);
        }
    }
}

// ---------------------------------------------------------------------------
// Kernel R: reduce NPART partials -> g_rsh (fp16)
// ---------------------------------------------------------------------------
__global__ __launch_bounds__(256) void reduce_r_kernel()
{
    size_t i = ((size_t)blockIdx.x * 256 + threadIdx.x) * 4;
    float4 a = *(const float4*)(g_r + i);
#pragma unroll
    for (int p = 1; p < NPART; p++) {
        float4 b = *(const float4*)(g_r + (size_t)p * NQ * DK + i);
        a.x += b.x; a.y += b.y; a.z += b.z; a.w += b.w;
    }
    *(uint2*)(g_rsh + i) = make_uint2(packh2(a.x, a.y), packh2(a.z, a.w));
}

// ---------------------------------------------------------------------------
// Kernel C: out = g_rsh @ WoT^T + bo   fp16 tensor-core GEMM.
// CTA = 64m x 128n, K=256 fully resident. 8 warps: mw=w&3 m16, nh=w>>2 n64.
// ---------------------------------------------------------------------------
#define OG_ASTR 264
#define OG_SMEM (64 * OG_ASTR * 2 + 128 * OG_ASTR * 2)

extern __shared__ char og_raw[];

__global__ __launch_bounds__(256, 1) void out_gemm_kernel(
    const float* __restrict__ bo, float* __restrict__ out)
{
    __half* As = (__half*)og_raw;            // [64][264]
    __half* Bs = As + 64 * OG_ASTR;          // [128][264]

    const int tid = threadIdx.x;
    const int w = tid >> 5, lane = tid & 31;
    const int t4 = lane >> 2, tq = lane & 3;
    const int mw = w & 3, nh = w >> 2;
    const int m0 = blockIdx.x * 64;
    const int n0 = blockIdx.y * 128;

    const int l15 = lane & 15, lh = lane >> 4;
    const u32 qa = s2u(As) + (u32)(((mw * 16 + l15) * OG_ASTR + lh * 8) * 2);
    const u32 qb = s2u(Bs) + (u32)(((nh * 64 + l15) * OG_ASTR + lh * 8) * 2);

#pragma unroll
    for (int u = 0; u < 8; u++) {   // A: 64 x 32 uint4
        int idx = tid + u * 256;
        int row = idx >> 5, seg = idx & 31;
        *(uint4*)(As + row * OG_ASTR + seg * 8) =
            *(const uint4*)(g_rsh + (size_t)(m0 + row) * DK + seg * 8);
    }
#pragma unroll
    for (int u = 0; u < 16; u++) {  // B: 128 x 32 uint4
        int idx = tid + u * 256;
        int row = idx >> 5, seg = idx & 31;
        *(uint4*)(Bs + row * OG_ASTR + seg * 8) =
            *(const uint4*)(g_woth + (size_t)(n0 + row) * DK + seg * 8);
    }
    __syncthreads();

    float acc[8][4];
#pragma unroll
    for (int nt = 0; nt < 8; nt++)
#pragma unroll
        for (int j = 0; j < 4; j++) acc[nt][j] = 0.f;

#pragma unroll
    for (int kk = 0; kk < 16; kk++) {
        u32 A[4];
        LDSM4(A, qa + kk * 32);
#pragma unroll
        for (int nt16 = 0; nt16 < 4; nt16++) {
            u32 B[4];
            LDSM4(B, qb + nt16 * 16 * OG_ASTR * 2 + kk * 32);
            mma_f16(acc[2 * nt16],     A[0], A[1], A[2], A[3], B[0], B[2]);
            mma_f16(acc[2 * nt16 + 1], A[0], A[1], A[2], A[3], B[1], B[3]);
        }
    }

    const int row = m0 + mw * 16 + t4;
#pragma unroll
    for (int nt = 0; nt < 8; nt++) {
        int col = n0 + nh * 64 + nt * 8 + 2 * tq;
        float2 bv = *(const float2*)(bo + col);
        *(float2*)(out + (size_t)row * DH + col) =
            make_float2(acc[nt][0] + bv.x, acc[nt][1] + bv.y);
        *(float2*)(out + (size_t)(row + 8) * DH + col) =
            make_float2(acc[nt][2] + bv.x, acc[nt][3] + bv.y);
    }
}

// ---------------------------------------------------------------------------
extern "C" void kernel_launch(void* const* d_in, const int* in_sizes, int n_in,
                              void* d_out, int out_size)
{
    const float* hs  = (const float*)d_in[0];
    const float* Wk  = (const float*)d_in[1];
    const float* bk  = (const float*)d_in[2];
    const float* lnw = (const float*)d_in[3];
    const float* lnb = (const float*)d_in[4];
    const float* mk  = (const float*)d_in[5];
    const float* mv  = (const float*)d_in[6];
    const float* Wo  = (const float*)d_in[7];
    const float* bo  = (const float*)d_in[8];
    const int* usage = (const int*)d_in[9];
    float* out = (float*)d_out;

    cudaFuncSetAttribute(attn_kernel, cudaFuncAttributeMaxDynamicSharedMemorySize,
                         ATTN_SMEM);
    cudaFuncSetAttribute(qproj_ln_kernel, cudaFuncAttributeMaxDynamicSharedMemorySize,
                         QP_SMEM);
    cudaFuncSetAttribute(out_gemm_kernel, cudaFuncAttributeMaxDynamicSharedMemorySize,
                         OG_SMEM);

    prep_kernel<<<PREP_GRID, 256>>>(mk, mv, hs, Wk, Wo);
    qproj_ln_kernel<<<NQ / 64, 256, QP_SMEM>>>(bk, lnw, lnb);
    attn_kernel<<<dim3(NQ / 64, NPART), 256, ATTN_SMEM>>>(usage);
    reduce_r_kernel<<<(NQ * DK) / (256 * 4), 256>>>();
    out_gemm_kernel<<<dim3(NQ / 64, DH / 128), 256, OG_SMEM>>>(bo, out);
}

// round 16
// speedup vs baseline: 1.3235x; 1.0464x over previous
#include <cuda_runtime.h>
#include <cuda_fp16.h>
#include <math.h>
#include <cstdint>

#define NBLK 32
#define CAP 1024
#define DK 256
#define DH 768
#define NQ 8192
#define NPART 32   /* one memory block per CTA */

typedef uint32_t u32;

// scratch (device globals: no allocation allowed)
__device__ __half g_qh[NQ * DK];              // layernormed queries * 1/16, fp16
__device__ __half g_kh[NBLK * CAP * DK];      // keys, fp16
__device__ __half g_vth[NBLK * DK * CAP];     // values transposed [b][d][key], fp16
__device__ __half g_hsh[NQ * DH];             // hidden states, fp16
__device__ __half g_wkth[DK * DH];            // Wk^T  [256][768], fp16
__device__ __half g_woth[DH * DK];            // Wo^T  [768][256], fp16
__device__ __half g_r[NPART * NQ * DK];       // per-block retrieved partials, fp16
__device__ __half g_rsh[NQ * DK];             // reduced retrieved values, fp16

__device__ __forceinline__ u32 packh2(float a, float b) {
    __half2 h = __floats2half2_rn(a, b);
    return *(u32*)&h;
}

// fp16 tensor-core mma, fp32 accumulate
__device__ __forceinline__ void mma_f16(float* d,
    u32 a0, u32 a1, u32 a2, u32 a3, u32 b0, u32 b1)
{
    asm("mma.sync.aligned.m16n8k16.row.col.f32.f16.f16.f32 "
        "{%0,%1,%2,%3},{%4,%5,%6,%7},{%8,%9},{%0,%1,%2,%3};"
        : "+f"(d[0]), "+f"(d[1]), "+f"(d[2]), "+f"(d[3])
        : "r"(a0), "r"(a1), "r"(a2), "r"(a3), "r"(b0), "r"(b1));
}

__device__ __forceinline__ u32 s2u(const void* p) {
    u32 a;
    asm("{ .reg .u64 t; cvta.to.shared.u64 t, %1; cvt.u32.u64 %0, t; }"
        : "=r"(a) : "l"(p));
    return a;
}
__device__ __forceinline__ void cpa16(u32 dst, const void* src) {
    asm volatile("cp.async.cg.shared.global [%0], [%1], 16;"
                 :: "r"(dst), "l"(src) : "memory");
}
#define CPA_COMMIT() asm volatile("cp.async.commit_group;" ::: "memory")
#define CPA_WAIT1()  asm volatile("cp.async.wait_group 1;" ::: "memory")

#define LDSM4(r, a) asm volatile( \
    "ldmatrix.sync.aligned.m8n8.x4.shared.b16 {%0,%1,%2,%3}, [%4];" \
    : "=r"((r)[0]), "=r"((r)[1]), "=r"((r)[2]), "=r"((r)[3]) : "r"(a))

// ---------------------------------------------------------------------------
// Kernel P (fused prep), roles by blockIdx.x:
//  keys->fp16 | V transpose->fp16 [b][d][key] | hs->fp16 | Wk^T | Wo^T
// ---------------------------------------------------------------------------
#define KH_BLOCKS  ((NBLK * CAP * DK) / (256 * 8))   /* 4096 */
#define VTH_BLOCKS ((DK / 32) * (CAP / 32) * NBLK)   /* 8192 */
#define HS_BLOCKS  ((NQ * DH) / (256 * 8))           /* 3072 */
#define WKT_BLOCKS ((DH / 32) * (DK / 32))           /* 192  */
#define WOT_BLOCKS ((DK / 32) * (DH / 32))           /* 192  */
#define PREP_GRID (KH_BLOCKS + VTH_BLOCKS + HS_BLOCKS + WKT_BLOCKS + WOT_BLOCKS)

__device__ __forceinline__ void tile_transpose(
    const float* __restrict__ in, __half* __restrict__ out,
    int R, int C, int rt, int ct, float t[32][33])
{
    const int r = threadIdx.x >> 3, c4 = (threadIdx.x & 7) * 4;
    float4 v = *(const float4*)(in + (size_t)(rt * 32 + r) * C + ct * 32 + c4);
    t[r][c4] = v.x; t[r][c4 + 1] = v.y; t[r][c4 + 2] = v.z; t[r][c4 + 3] = v.w;
    __syncthreads();
    uint2 o = make_uint2(packh2(t[c4][r], t[c4 + 1][r]),
                         packh2(t[c4 + 2][r], t[c4 + 3][r]));
    *(uint2*)(out + (size_t)(ct * 32 + r) * R + rt * 32 + c4) = o;
}

__global__ __launch_bounds__(256) void prep_kernel(
    const float* __restrict__ mk, const float* __restrict__ mv,
    const float* __restrict__ hs, const float* __restrict__ Wk,
    const float* __restrict__ Wo)
{
    __shared__ float t[32][33];
    int bx = blockIdx.x;
    if (bx < KH_BLOCKS) {
        size_t i = ((size_t)bx * 256 + threadIdx.x) * 8;
        float4 v0 = *(const float4*)(mk + i);
        float4 v1 = *(const float4*)(mk + i + 4);
        *(uint4*)(g_kh + i) = make_uint4(packh2(v0.x, v0.y), packh2(v0.z, v0.w),
                                         packh2(v1.x, v1.y), packh2(v1.z, v1.w));
        return;
    }
    bx -= KH_BLOCKS;
    if (bx < VTH_BLOCKS) {
        const int dt = bx & 7, kt = (bx >> 3) & 31, b = bx >> 8;
        tile_transpose(mv + (size_t)b * CAP * DK, g_vth + (size_t)b * DK * CAP,
                       CAP, DK, kt, dt, t);
        return;
    }
    bx -= VTH_BLOCKS;
    if (bx < HS_BLOCKS) {
        size_t i = ((size_t)bx * 256 + threadIdx.x) * 8;
        float4 v0 = *(const float4*)(hs + i);
        float4 v1 = *(const float4*)(hs + i + 4);
        *(uint4*)(g_hsh + i) = make_uint4(packh2(v0.x, v0.y), packh2(v0.z, v0.w),
                                          packh2(v1.x, v1.y), packh2(v1.z, v1.w));
        return;
    }
    bx -= HS_BLOCKS;
    if (bx < WKT_BLOCKS) {
        const int ct = bx & 7, rt = bx >> 3;   // Wk: R=768, C=256
        tile_transpose(Wk, g_wkth, DH, DK, rt, ct, t);
        return;
    }
    bx -= WKT_BLOCKS;
    {
        const int ct = bx % 24, rt = bx / 24;  // Wo: R=256, C=768
        tile_transpose(Wo, g_woth, DK, DH, rt, ct, t);
    }
}

// ---------------------------------------------------------------------------
// Kernel A: q = LayerNorm(hsh @ WkT + bk) * ln_w + ln_b, scaled 1/16 -> fp16
// fp16 tensor-core GEMM (R15 proven).
// ---------------------------------------------------------------------------
#define QP_ASTR 136
#define QP_SMEM (1024 + 64 * QP_ASTR * 2 + 256 * QP_ASTR * 2)

extern __shared__ char qp_raw[];

__global__ __launch_bounds__(256, 1) void qproj_ln_kernel(
    const float* __restrict__ bk, const float* __restrict__ lnw,
    const float* __restrict__ lnb)
{
    float*  Lq = (float*)qp_raw;
    __half* As = (__half*)(qp_raw + 1024);
    __half* Bs = As + 64 * QP_ASTR;

    const int tid = threadIdx.x;
    const int w = tid >> 5, lane = tid & 31;
    const int t4 = lane >> 2, tq = lane & 3;
    const int mw = w & 3, nh = w >> 2;
    const int m0 = blockIdx.x * 64;

    const int l15 = lane & 15, lh = lane >> 4;
    const u32 qa = s2u(As) + (u32)(((mw * 16 + l15) * QP_ASTR + lh * 8) * 2);
    const u32 qb = s2u(Bs) + (u32)(((nh * 128 + l15) * QP_ASTR + lh * 8) * 2);

    float acc[16][4];
#pragma unroll
    for (int nt = 0; nt < 16; nt++)
#pragma unroll
        for (int j = 0; j < 4; j++) acc[nt][j] = 0.f;

    for (int kc = 0; kc < DH / 128; kc++) {
        const int k0 = kc * 128;
#pragma unroll
        for (int u = 0; u < 4; u++) {
            int idx = tid + u * 256;
            int row = idx >> 4, seg = idx & 15;
            *(uint4*)(As + row * QP_ASTR + seg * 8) =
                *(const uint4*)(g_hsh + (size_t)(m0 + row) * DH + k0 + seg * 8);
        }
#pragma unroll
        for (int u = 0; u < 16; u++) {
            int idx = tid + u * 256;
            int row = idx >> 4, seg = idx & 15;
            *(uint4*)(Bs + row * QP_ASTR + seg * 8) =
                *(const uint4*)(g_wkth + (size_t)row * DH + k0 + seg * 8);
        }
        __syncthreads();
#pragma unroll
        for (int kk = 0; kk < 8; kk++) {
            u32 A[4];
            LDSM4(A, qa + kk * 32);
#pragma unroll
            for (int nt16 = 0; nt16 < 8; nt16++) {
                u32 B[4];
                LDSM4(B, qb + nt16 * 16 * QP_ASTR * 2 + kk * 32);
                mma_f16(acc[2 * nt16],     A[0], A[1], A[2], A[3], B[0], B[2]);
                mma_f16(acc[2 * nt16 + 1], A[0], A[1], A[2], A[3], B[1], B[3]);
            }
        }
        __syncthreads();
    }

    const int row = mw * 16 + t4;
    float slo = 0.f, sqlo = 0.f, shi = 0.f, sqhi = 0.f;
#pragma unroll
    for (int nt = 0; nt < 16; nt++) {
        int col = nh * 128 + nt * 8 + 2 * tq;
        float2 bkv = *(const float2*)(bk + col);
        acc[nt][0] += bkv.x; acc[nt][1] += bkv.y;
        acc[nt][2] += bkv.x; acc[nt][3] += bkv.y;
        slo += acc[nt][0] + acc[nt][1];
        sqlo += acc[nt][0] * acc[nt][0] + acc[nt][1] * acc[nt][1];
        shi += acc[nt][2] + acc[nt][3];
        sqhi += acc[nt][2] * acc[nt][2] + acc[nt][3] * acc[nt][3];
    }
#pragma unroll
    for (int o = 1; o <= 2; o <<= 1) {
        slo  += __shfl_xor_sync(0xffffffffu, slo, o);
        sqlo += __shfl_xor_sync(0xffffffffu, sqlo, o);
        shi  += __shfl_xor_sync(0xffffffffu, shi, o);
        sqhi += __shfl_xor_sync(0xffffffffu, sqhi, o);
    }
    if (tq == 0) {
        Lq[row * 4 + nh * 2]           = slo;
        Lq[row * 4 + nh * 2 + 1]       = sqlo;
        Lq[(row + 8) * 4 + nh * 2]     = shi;
        Lq[(row + 8) * 4 + nh * 2 + 1] = sqhi;
    }
    __syncthreads();

    float mu0, rs0, mu1, rs1;
    {
        float s = Lq[row * 4] + Lq[row * 4 + 2];
        float q = Lq[row * 4 + 1] + Lq[row * 4 + 3];
        mu0 = s * (1.0f / 256.0f);
        rs0 = rsqrtf(q * (1.0f / 256.0f) - mu0 * mu0 + 1e-5f);
        s = Lq[(row + 8) * 4] + Lq[(row + 8) * 4 + 2];
        q = Lq[(row + 8) * 4 + 1] + Lq[(row + 8) * 4 + 3];
        mu1 = s * (1.0f / 256.0f);
        rs1 = rsqrtf(q * (1.0f / 256.0f) - mu1 * mu1 + 1e-5f);
    }
#pragma unroll
    for (int nt = 0; nt < 16; nt++) {
        int col = nh * 128 + nt * 8 + 2 * tq;
        float2 lw = *(const float2*)(lnw + col);
        float2 lb = *(const float2*)(lnb + col);
        float o0 = ((acc[nt][0] - mu0) * rs0 * lw.x + lb.x) * 0.0625f;
        float o1 = ((acc[nt][1] - mu0) * rs0 * lw.y + lb.y) * 0.0625f;
        float o2 = ((acc[nt][2] - mu1) * rs1 * lw.x + lb.x) * 0.0625f;
        float o3 = ((acc[nt][3] - mu1) * rs1 * lw.y + lb.y) * 0.0625f;
        *(u32*)(g_qh + (size_t)(m0 + row) * DK + col)     = packh2(o0, o1);
        *(u32*)(g_qh + (size_t)(m0 + row + 8) * DK + col) = packh2(o2, o3);
    }
}

// ---------------------------------------------------------------------------
// Kernel B: attention, ONE memory block per CTA (grid 128 x 32), chunk = 32
// keys, double-buffered cp.async, 256 threads, TWO CTAs per SM
// (__launch_bounds__(256,2) caps regs at 128: acc is the block result,
// no running O accumulator needed).
// QK: warp w -> m16 tile (w>>1), key-half n16 (w&1); k=256.
// PV: warp w -> m32 group (w&1), col group n64 (w>>1); k=32.
// ---------------------------------------------------------------------------
#define QSTR 264
#define KSTR 264
#define VSTR 40
#define PSTR 40
#define KBUF (32 * KSTR)
#define VBUF (256 * VSTR)
#define ATTN_SMEM (512 + 64*QSTR*2 + 2*KBUF*2 + 2*VBUF*2 + 64*PSTR*2)

extern __shared__ char sm_raw[];

__global__ void __launch_bounds__(256, 2) attn_kernel(const int* __restrict__ usage)
{
    float*  Ls  = (float*)sm_raw;                 // [64][2]
    __half* Qs  = (__half*)(sm_raw + 512);        // [64][264]
    __half* Ks  = Qs + 64 * QSTR;                 // 2 x [32][264]
    __half* Vts = Ks + 2 * KBUF;                  // 2 x [256][40]
    __half* Ps  = Vts + 2 * VBUF;                 // [64][40]

    const u32 ks_u = s2u(Ks);
    const u32 vt_u = s2u(Vts);

    const int tid  = threadIdx.x;
    const int w    = tid >> 5;
    const int lane = tid & 31;
    const int t4   = lane >> 2;
    const int tq   = lane & 3;
    const int q0   = blockIdx.x * 64;
    const int b    = blockIdx.y;

    const int mw = w >> 1;          // QK m16 tile
    const int nh = w & 1;           // QK key-half (n16)
    const int mg = w & 1;           // PV m32 group
    const int ng = w >> 1;          // PV n64 group

    const int l15 = lane & 15, lh = lane >> 4;
    const u32 qa  = s2u(Qs) + (u32)(((mw * 16 + l15) * QSTR + lh * 8) * 2);
    const u32 kb0 = (u32)(((nh * 16 + l15) * KSTR + lh * 8) * 2);   // + ks_u + buf
    const u32 pa0 = s2u(Ps) + (u32)(((mg * 32 + l15) * PSTR + lh * 8) * 2);
    const u32 pa1 = pa0 + 16 * PSTR * 2;
    const u32 vb0 = (u32)(((ng * 64 + l15) * VSTR + lh * 8) * 2);   // + vt_u + buf

    // Q tile -> smem
#pragma unroll
    for (int u = 0; u < 8; u++) {
        int idx = tid + u * 256;
        int row = idx >> 5, seg = idx & 31;
        uint4 v = *(const uint4*)(g_qh + ((size_t)(q0 + row) << 8) + seg * 8);
        *(uint4*)(Qs + row * QSTR + seg * 8) = v;
    }

    const int use = __ldg(usage + b);
    const int nch = (use + 31) >> 5;
    const __half* kgb = g_kh + (size_t)b * CAP * DK;
    const __half* vgb = g_vth + (size_t)b * DK * CAP;

    // prefetch chunk 0 into buffer 0
#pragma unroll
    for (int u = 0; u < 4; u++) {
        int idx = tid + u * 256;
        int key = idx >> 5, seg = idx & 31;
        cpa16(ks_u + (key * KSTR + seg * 8) * 2, kgb + (size_t)key * DK + seg * 8);
        int d = idx >> 2, sg = idx & 3;
        cpa16(vt_u + (d * VSTR + sg * 8) * 2, vgb + (size_t)d * CAP + sg * 8);
    }
    CPA_COMMIT();

    float acc[2][8][4];
#pragma unroll
    for (int mt = 0; mt < 2; mt++)
#pragma unroll
        for (int nt = 0; nt < 8; nt++)
#pragma unroll
            for (int j = 0; j < 4; j++) acc[mt][nt][j] = 0.f;

    for (int ch = 0; ch < nch; ch++) {
        const int buf = ch & 1;
        const int c0 = ch * 32;

        __syncthreads();   // A: prev chunk fully consumed -> buf^1 free

        // prefetch next chunk into buf^1
        if (ch + 1 < nch) {
            const int pb = buf ^ 1;
            const __half* kg = kgb + (size_t)(c0 + 32) * DK;
            const __half* vg = vgb + (c0 + 32);
            const u32 kd = ks_u + pb * KBUF * 2;
            const u32 vd = vt_u + pb * VBUF * 2;
#pragma unroll
            for (int u = 0; u < 4; u++) {
                int idx = tid + u * 256;
                int key = idx >> 5, seg = idx & 31;
                cpa16(kd + (key * KSTR + seg * 8) * 2, kg + (size_t)key * DK + seg * 8);
                int d = idx >> 2, sg = idx & 3;
                cpa16(vd + (d * VSTR + sg * 8) * 2, vg + (size_t)d * CAP + sg * 8);
            }
        }
        CPA_COMMIT();
        CPA_WAIT1();       // current chunk complete
        __syncthreads();   // B: chunk data visible

        // ---- S = Q K^T : m16 x n16 over k=256 ----
        const u32 kbase = ks_u + buf * KBUF * 2 + kb0;
        float s[2][4];
#pragma unroll
        for (int nt = 0; nt < 2; nt++)
#pragma unroll
            for (int j = 0; j < 4; j++) s[nt][j] = 0.f;
#pragma unroll
        for (int kk = 0; kk < 16; kk++) {
            u32 A[4], B[4];
            LDSM4(A, qa + kk * 32);
            LDSM4(B, kbase + kk * 32);
            mma_f16(s[0], A[0], A[1], A[2], A[3], B[0], B[2]);
            mma_f16(s[1], A[0], A[1], A[2], A[3], B[1], B[3]);
        }

        // ---- mask + exp + store P + row-sum partials ----
        const int rem = use - c0;   // >= 1
        const int row = mw * 16 + t4;
        float rs_lo = 0.f, rs_hi = 0.f;
#pragma unroll
        for (int nt = 0; nt < 2; nt++) {
            int col = nh * 16 + nt * 8 + 2 * tq;
            float p0 = (col     < rem) ? __expf(s[nt][0]) : 0.f;
            float p1 = (col + 1 < rem) ? __expf(s[nt][1]) : 0.f;
            float p2 = (col     < rem) ? __expf(s[nt][2]) : 0.f;
            float p3 = (col + 1 < rem) ? __expf(s[nt][3]) : 0.f;
            rs_lo += p0 + p1;
            rs_hi += p2 + p3;
            *(u32*)(Ps + row * PSTR + col)       = packh2(p0, p1);
            *(u32*)(Ps + (row + 8) * PSTR + col) = packh2(p2, p3);
        }
        rs_lo += __shfl_xor_sync(0xffffffffu, rs_lo, 1);
        rs_lo += __shfl_xor_sync(0xffffffffu, rs_lo, 2);
        rs_hi += __shfl_xor_sync(0xffffffffu, rs_hi, 1);
        rs_hi += __shfl_xor_sync(0xffffffffu, rs_hi, 2);
        if (tq == 0) {   // unique writer per (row, key-half)
            if (ch == 0) {
                Ls[row * 2 + nh]       = rs_lo;
                Ls[(row + 8) * 2 + nh] = rs_hi;
            } else {
                Ls[row * 2 + nh]       += rs_lo;
                Ls[(row + 8) * 2 + nh] += rs_hi;
            }
        }
        __syncthreads();   // C: P + Ls visible

        // ---- acc += P @ V : m32 x n64 over k=32 ----
        const u32 vbase = vt_u + buf * VBUF * 2 + vb0;
#pragma unroll
        for (int kk = 0; kk < 2; kk++) {
            u32 A0[4], A1[4];
            LDSM4(A0, pa0 + kk * 32);
            LDSM4(A1, pa1 + kk * 32);
#pragma unroll
            for (int nt = 0; nt < 4; nt++) {
                u32 B[4];
                LDSM4(B, vbase + nt * 16 * VSTR * 2 + kk * 32);
                mma_f16(acc[0][2 * nt],     A0[0], A0[1], A0[2], A0[3], B[0], B[2]);
                mma_f16(acc[0][2 * nt + 1], A0[0], A0[1], A0[2], A0[3], B[1], B[3]);
                mma_f16(acc[1][2 * nt],     A1[0], A1[1], A1[2], A1[3], B[0], B[2]);
                mma_f16(acc[1][2 * nt + 1], A1[0], A1[1], A1[2], A1[3], B[1], B[3]);
            }
        }
    }

    // ---- finalize: write acc / rowsum as fp16 partial for this block ----
    __half* dst = g_r + (size_t)b * NQ * DK;
#pragma unroll
    for (int mt = 0; mt < 2; mt++) {
        int r = mg * 32 + mt * 16 + t4;
        float il = 1.0f / (Ls[r * 2] + Ls[r * 2 + 1]);
        float ih = 1.0f / (Ls[(r + 8) * 2] + Ls[(r + 8) * 2 + 1]);
#pragma unroll
        for (int nt = 0; nt < 8; nt++) {
            int col = ng * 64 + nt * 8 + 2 * tq;
            *(u32*)(dst + (size_t)(q0 + r) * DK + col) =
                packh2(acc[mt][nt][0] * il, acc[mt][nt][1] * il);
            *(u32*)(dst + (size_t)(q0 + r + 8) * DK + col) =
                packh2(acc[mt][nt][2] * ih, acc[mt][nt][3] * ih);
        }
    }
}

// ---------------------------------------------------------------------------
// Kernel R: reduce 32 fp16 partials -> g_rsh (fp16)
// ---------------------------------------------------------------------------
__global__ __launch_bounds__(256) void reduce_r_kernel()
{
    size_t i = ((size_t)blockIdx.x * 256 + threadIdx.x) * 8;
    float a[8];
#pragma unroll
    for (int j = 0; j < 8; j++) a[j] = 0.f;
#pragma unroll
    for (int p = 0; p < NPART; p++) {
        uint4 v = *(const uint4*)(g_r + (size_t)p * NQ * DK + i);
        const __half2* h = (const __half2*)&v;
#pragma unroll
        for (int j = 0; j < 4; j++) {
            float2 f = __half22float2(h[j]);
            a[2 * j] += f.x; a[2 * j + 1] += f.y;
        }
    }
    *(uint4*)(g_rsh + i) = make_uint4(packh2(a[0], a[1]), packh2(a[2], a[3]),
                                      packh2(a[4], a[5]), packh2(a[6], a[7]));
}

// ---------------------------------------------------------------------------
// Kernel C: out = g_rsh @ WoT^T + bo   fp16 tensor-core GEMM (R15 proven).
// ---------------------------------------------------------------------------
#define OG_ASTR 264
#define OG_SMEM (64 * OG_ASTR * 2 + 128 * OG_ASTR * 2)

extern __shared__ char og_raw[];

__global__ __launch_bounds__(256, 1) void out_gemm_kernel(
    const float* __restrict__ bo, float* __restrict__ out)
{
    __half* As = (__half*)og_raw;
    __half* Bs = As + 64 * OG_ASTR;

    const int tid = threadIdx.x;
    const int w = tid >> 5, lane = tid & 31;
    const int t4 = lane >> 2, tq = lane & 3;
    const int mw = w & 3, nh = w >> 2;
    const int m0 = blockIdx.x * 64;
    const int n0 = blockIdx.y * 128;

    const int l15 = lane & 15, lh = lane >> 4;
    const u32 qa = s2u(As) + (u32)(((mw * 16 + l15) * OG_ASTR + lh * 8) * 2);
    const u32 qb = s2u(Bs) + (u32)(((nh * 64 + l15) * OG_ASTR + lh * 8) * 2);

#pragma unroll
    for (int u = 0; u < 8; u++) {
        int idx = tid + u * 256;
        int row = idx >> 5, seg = idx & 31;
        *(uint4*)(As + row * OG_ASTR + seg * 8) =
            *(const uint4*)(g_rsh + (size_t)(m0 + row) * DK + seg * 8);
    }
#pragma unroll
    for (int u = 0; u < 16; u++) {
        int idx = tid + u * 256;
        int row = idx >> 5, seg = idx & 31;
        *(uint4*)(Bs + row * OG_ASTR + seg * 8) =
            *(const uint4*)(g_woth + (size_t)(n0 + row) * DK + seg * 8);
    }
    __syncthreads();

    float acc[8][4];
#pragma unroll
    for (int nt = 0; nt < 8; nt++)
#pragma unroll
        for (int j = 0; j < 4; j++) acc[nt][j] = 0.f;

#pragma unroll
    for (int kk = 0; kk < 16; kk++) {
        u32 A[4];
        LDSM4(A, qa + kk * 32);
#pragma unroll
        for (int nt16 = 0; nt16 < 4; nt16++) {
            u32 B[4];
            LDSM4(B, qb + nt16 * 16 * OG_ASTR * 2 + kk * 32);
            mma_f16(acc[2 * nt16],     A[0], A[1], A[2], A[3], B[0], B[2]);
            mma_f16(acc[2 * nt16 + 1], A[0], A[1], A[2], A[3], B[1], B[3]);
        }
    }

    const int row = m0 + mw * 16 + t4;
#pragma unroll
    for (int nt = 0; nt < 8; nt++) {
        int col = n0 + nh * 64 + nt * 8 + 2 * tq;
        float2 bv = *(const float2*)(bo + col);
        *(float2*)(out + (size_t)row * DH + col) =
            make_float2(acc[nt][0] + bv.x, acc[nt][1] + bv.y);
        *(float2*)(out + (size_t)(row + 8) * DH + col) =
            make_float2(acc[nt][2] + bv.x, acc[nt][3] + bv.y);
    }
}

// ---------------------------------------------------------------------------
extern "C" void kernel_launch(void* const* d_in, const int* in_sizes, int n_in,
                              void* d_out, int out_size)
{
    const float* hs  = (const float*)d_in[0];
    const float* Wk  = (const float*)d_in[1];
    const float* bk  = (const float*)d_in[2];
    const float* lnw = (const float*)d_in[3];
    const float* lnb = (const float*)d_in[4];
    const float* mk  = (const float*)d_in[5];
    const float* mv  = (const float*)d_in[6];
    const float* Wo  = (const float*)d_in[7];
    const float* bo  = (const float*)d_in[8];
    const int* usage = (const int*)d_in[9];
    float* out = (float*)d_out;

    cudaFuncSetAttribute(attn_kernel, cudaFuncAttributeMaxDynamicSharedMemorySize,
                         ATTN_SMEM);
    cudaFuncSetAttribute(qproj_ln_kernel, cudaFuncAttributeMaxDynamicSharedMemorySize,
                         QP_SMEM);
    cudaFuncSetAttribute(out_gemm_kernel, cudaFuncAttributeMaxDynamicSharedMemorySize,
                         OG_SMEM);

    prep_kernel<<<PREP_GRID, 256>>>(mk, mv, hs, Wk, Wo);
    qproj_ln_kernel<<<NQ / 64, 256, QP_SMEM>>>(bk, lnw, lnb);
    attn_kernel<<<dim3(NQ / 64, NPART), 256, ATTN_SMEM>>>(usage);
    reduce_r_kernel<<<(NQ * DK) / (256 * 8), 256>>>();
    out_gemm_kernel<<<dim3(NQ / 64, DH / 128), 256, OG_SMEM>>>(bo, out);
}